// round 10
// baseline (speedup 1.0000x reference)
#include <cuda_runtime.h>
#include <cstdint>

#define TABLE_ROWS 1025
#define HIDDEN     128
#define SEQ        512
#define BATCH      2
#define MAXSEQ     512
#define R_MAX      44        // max contiguous table rows cached per table per tile
#define PROD_BLOCKS  129     // blocks that also run the projection (8 rows each)
#define TOTAL_BLOCKS 2048    // (SEQ/16)*(SEQ/16)*BATCH

// Scratch + sync state (allocation-free rule: device globals, zero-initialized).
__device__ float g_Ass[TABLE_ROWS * HIDDEN];   // pe_ss @ W[:, :128]^T + bias
__device__ float g_Aee[TABLE_ROWS * HIDDEN];   // pe_ee @ W[:, 128:]^T
__device__ unsigned int g_ready;               // producers finished
__device__ unsigned int g_exit;                // blocks exited (for self-reset)

// ---------------------------------------------------------------------------
// Helpers
// ---------------------------------------------------------------------------
__device__ __forceinline__ void cp_async16(uint32_t saddr, const void* gaddr)
{
    asm volatile("cp.async.cg.shared.global [%0], [%1], 16;"
                 :: "r"(saddr), "l"(gaddr) : "memory");
}

// Predicated LDS.128: load only if row != prev (warp-uniform condition);
// otherwise keep the previous value already in the registers.
__device__ __forceinline__ void lds_if(float4& v, uint32_t saddr, int row, int prev)
{
    asm volatile(
        "{\n\t.reg .pred p;\n\t"
        "setp.ne.s32 p, %4, %5;\n\t"
        "@p ld.shared.v4.f32 {%0, %1, %2, %3}, [%6];\n\t}"
        : "+f"(v.x), "+f"(v.y), "+f"(v.z), "+f"(v.w)
        : "r"(row), "r"(prev), "r"(saddr));
}

__device__ __forceinline__ unsigned int ld_acquire_gpu(const unsigned int* p)
{
    unsigned int v;
    asm volatile("ld.acquire.gpu.global.u32 %0, [%1];" : "=r"(v) : "l"(p));
    return v;
}

// ---------------------------------------------------------------------------
// Single fused kernel.
// Phase 1 (blocks flat < 129): projection, R1-measured-best form, both table
//   halves at once (sel = tid>>7). pe rows staged in the sA SMEM region
//   (reused later by the gather phase).
// Sync: g_ready flag; all blocks spin until the table is complete. Producers
//   are the lowest 129 linear block ids -> guaranteed in wave 1 (>=3 CTA/SM).
// Phase 2: gather, EXACT R6 configuration (measured best, 43.8/43.9 us).
// Epilogue: last block resets counters so graph replays stay deterministic.
// ---------------------------------------------------------------------------
__global__ void __launch_bounds__(256)
fused_kernel(const int* __restrict__ pos_s,
             const int* __restrict__ pos_e,
             const float* __restrict__ pe_ss,
             const float* __restrict__ pe_ee,
             const float* __restrict__ W,
             const float* __restrict__ bias,
             float* __restrict__ out)
{
    const int b    = blockIdx.z;
    const int i0   = blockIdx.y * 16;
    const int j0   = blockIdx.x * 16;
    const int flat = blockIdx.x + blockIdx.y * (SEQ / 16) +
                     blockIdx.z * (SEQ / 16) * (SEQ / 16);

    __shared__ float4 sA[R_MAX * 32];       // 22.5 KB (also pe staging in phase 1)
    __shared__ float4 sE[R_MAX * 32];       // 22.5 KB
    __shared__ int s_psi[16], s_pei[16], s_psj[16], s_pej[16];
    __shared__ int s_meta[4];               // loA, nA(0=fallback), loE, nE

    const int tid = threadIdx.x;

    // ---------------- Phase 1: projection (producer blocks only) ----------
    if (flat < PROD_BLOCKS) {
        const int t0  = flat * 8;
        const int h   = tid & 127;
        const int sel = tid >> 7;           // 0 -> ss(+bias), 1 -> ee

        const float* __restrict__ pe = sel ? pe_ee : pe_ss;
        float* __restrict__ outA     = sel ? g_Aee : g_Ass;
        float* pes = reinterpret_cast<float*>(sA) + sel * (8 * HIDDEN);

        #pragma unroll
        for (int r = 0; r < 8; r++) {
            const int t = t0 + r;
            pes[r * HIDDEN + h] = (t < TABLE_ROWS) ? pe[(size_t)t * HIDDEN + h] : 0.0f;
        }
        __syncthreads();

        float acc[8];
        const float binit = sel ? 0.0f : bias[h];
        #pragma unroll
        for (int r = 0; r < 8; r++) acc[r] = binit;

        const float4* __restrict__ W4 = reinterpret_cast<const float4*>(
            W + (size_t)h * (2 * HIDDEN) + sel * HIDDEN);

        #pragma unroll 8
        for (int kg = 0; kg < HIDDEN / 4; kg++) {
            const float4 w = W4[kg];
            #pragma unroll
            for (int r = 0; r < 8; r++) {
                const float4 p =
                    reinterpret_cast<const float4*>(pes + r * HIDDEN)[kg]; // broadcast
                acc[r] += w.x * p.x + w.y * p.y + w.z * p.z + w.w * p.w;
            }
        }

        #pragma unroll
        for (int r = 0; r < 8; r++) {
            const int t = t0 + r;
            if (t < TABLE_ROWS) outA[(size_t)t * HIDDEN + h] = acc[r];
        }

        __threadfence();                    // publish table rows gpu-wide
        __syncthreads();                    // all threads' fences done
        if (tid == 0) atomicAdd(&g_ready, 1u);
        __syncthreads();                    // sA safe to reuse below
    }

    // ---------------- Common: stage positions + tile metadata -------------
    if (tid < 16) {
        s_psi[tid] = pos_s[b * SEQ + i0 + tid];
        s_pei[tid] = pos_e[b * SEQ + i0 + tid];
        s_psj[tid] = pos_s[b * SEQ + j0 + tid];
        s_pej[tid] = pos_e[b * SEQ + j0 + tid];
    }
    __syncthreads();

    if (tid == 0) {
        int lo = s_psi[0]  - s_psj[15] + MAXSEQ;   // sorted: endpoints = extrema
        int n  = (s_psi[15] - s_psj[0] + MAXSEQ) - lo + 1;
        s_meta[0] = lo;
        s_meta[1] = (n <= R_MAX) ? n : 0;
        lo = s_pei[0]  - s_pej[15] + MAXSEQ;
        n  = (s_pei[15] - s_pej[0] + MAXSEQ) - lo + 1;
        s_meta[2] = lo;
        s_meta[3] = (n <= R_MAX) ? n : 0;

        // Wait for the full projected tables.
        while (ld_acquire_gpu(&g_ready) < (unsigned)PROD_BLOCKS)
            __nanosleep(128);
    }
    __syncthreads();

    const int loA = s_meta[0], nA = s_meta[1];
    const int loE = s_meta[2], nE = s_meta[3];

    const float4* __restrict__ gA = reinterpret_cast<const float4*>(g_Ass);
    const float4* __restrict__ gE = reinterpret_cast<const float4*>(g_Aee);

    const uint32_t sA_base = (uint32_t)__cvta_generic_to_shared(sA);
    const uint32_t sE_base = (uint32_t)__cvta_generic_to_shared(sE);

    const int warp = tid >> 5;
    const int lane = tid & 31;

    // ---------------- Phase 2: gather (EXACT R6 body) ---------------------
    if (nA && nE) {
        for (int t = tid; t < nA * 32; t += 256)
            cp_async16(sA_base + t * 16, gA + loA * 32 + t);
        for (int t = tid; t < nE * 32; t += 256)
            cp_async16(sE_base + t * 16, gE + loE * 32 + t);
        asm volatile("cp.async.commit_group;\ncp.async.wait_group 0;" ::: "memory");
        __syncthreads();

        #pragma unroll
        for (int half = 0; half < 2; half++) {
            const int ii = warp * 2 + half;
            const int baseA = s_psi[ii] + MAXSEQ - loA;   // row = baseA - psj
            const int baseE = s_pei[ii] + MAXSEQ - loE;
            float4* __restrict__ orow = reinterpret_cast<float4*>(out) +
                (((size_t)b * SEQ + (i0 + ii)) * SEQ + j0) * (HIDDEN / 4) + lane;

            int prevA = -1, prevE = -1;
            float4 a = make_float4(0.f, 0.f, 0.f, 0.f);
            float4 e = make_float4(0.f, 0.f, 0.f, 0.f);

            #pragma unroll
            for (int jj = 0; jj < 16; jj++) {
                const int rA = baseA - s_psj[jj];         // warp-uniform
                const int rE = baseE - s_pej[jj];

                lds_if(a, sA_base + (rA * 32 + lane) * 16, rA, prevA);
                lds_if(e, sE_base + (rE * 32 + lane) * 16, rE, prevE);
                prevA = rA;
                prevE = rE;

                float4 r;
                r.x = fmaxf(a.x + e.x, 0.0f);
                r.y = fmaxf(a.y + e.y, 0.0f);
                r.z = fmaxf(a.z + e.z, 0.0f);
                r.w = fmaxf(a.w + e.w, 0.0f);

                orow[jj * (HIDDEN / 4)] = r;
            }
        }
    } else {
        // Cold path: range too wide for SMEM — direct global gathers.
        #pragma unroll
        for (int half = 0; half < 2; half++) {
            const int ii  = warp * 2 + half;
            const int psi = s_psi[ii];
            const int pei = s_pei[ii];
            float4* __restrict__ orow = reinterpret_cast<float4*>(out) +
                (((size_t)b * SEQ + (i0 + ii)) * SEQ + j0) * (HIDDEN / 4) + lane;

            for (int jj = 0; jj < 16; jj++) {
                const int iss = psi - s_psj[jj] + MAXSEQ;
                const int iee = pei - s_pej[jj] + MAXSEQ;
                const float4 a = __ldg(gA + iss * 32 + lane);
                const float4 e = __ldg(gE + iee * 32 + lane);
                float4 r;
                r.x = fmaxf(a.x + e.x, 0.0f);
                r.y = fmaxf(a.y + e.y, 0.0f);
                r.z = fmaxf(a.z + e.z, 0.0f);
                r.w = fmaxf(a.w + e.w, 0.0f);
                orow[jj * (HIDDEN / 4)] = r;
            }
        }
    }

    // ---------------- Epilogue: self-resetting counters --------------------
    __syncthreads();
    if (tid == 0) {
        const unsigned int n = atomicAdd(&g_exit, 1u);
        if (n == (unsigned)(TOTAL_BLOCKS - 1)) {
            g_ready = 0u;           // all blocks are past the spin; safe to reset
            g_exit  = 0u;
            __threadfence();
        }
    }
}

// ---------------------------------------------------------------------------
// Inputs (metadata order): 0 pos_s [B,S] i32, 1 pos_e [B,S] i32,
// 2 pe_ss [1025,128] f32, 3 pe_se (unused), 4 pe_es (unused),
// 5 pe_ee [1025,128] f32, 6 W [128,256] f32, 7 b [128] f32.
// Output: [B,S,S,H] f32.
// ---------------------------------------------------------------------------
extern "C" void kernel_launch(void* const* d_in, const int* in_sizes, int n_in,
                              void* d_out, int out_size)
{
    const int*   pos_s = (const int*)d_in[0];
    const int*   pos_e = (const int*)d_in[1];
    const float* pe_ss = (const float*)d_in[2];
    const float* pe_ee = (const float*)d_in[5];
    const float* W     = (const float*)d_in[6];
    const float* bias  = (const float*)d_in[7];
    float*       out   = (float*)d_out;

    dim3 grid(SEQ / 16, SEQ / 16, BATCH);   // 2048 blocks
    fused_kernel<<<grid, 256>>>(pos_s, pos_e, pe_ss, pe_ee, W, bias, out);
}